// round 7
// baseline (speedup 1.0000x reference)
#include <cuda_runtime.h>
#include <cuda_fp16.h>

// ---------------------------------------------------------------------------
// CausalEdgeAttention — algebraically reduced.
//   out = edge_attr + 0.5*((relu(ctx@W1+b1) * g) @ M + const8)
//   ctx = 0.5*(nf[src]+nf[tgt]);  M = n_W2@Wv@Wo@Wp (256x8)
// R6: identical design to R5 (infra failure, not kernel verdict):
//   pass1 stores r=relu(h) as fp16 (256MB __device__ scratch); pass2 streams
//   r instead of recomputing GEMM1. g_h now __align__(16) (uint4 reads).
// ---------------------------------------------------------------------------

#define STATS_BLOCKS 1184              // 8 blocks/SM * 148 SMs, one wave
#define STATS_WARPS  (STATS_BLOCKS * 4)
#define E_MAX 500224

__device__ __align__(16) float g_U[256 * 8];
__device__ __align__(16) float g_V[256 * 8];
__device__ __align__(16) float g_M[256 * 8];
__device__ __align__(16) float g_Mgp[128 * 16];   // permuted g*M, word-major
__device__ float g_c1[256];
__device__ float g_c2[256];
__device__ float g_c3[8];
__device__ __align__(16) float g_const8[8];
__device__ __align__(16) float g_part[STATS_BLOCKS * 512];
__device__ __align__(16) unsigned g_h[(size_t)E_MAX * 128]; // fp16x2 relu(h)

// ---- packed f32x2 helpers -------------------------------------------------
__device__ __forceinline__ unsigned long long pk2(float lo, float hi) {
    unsigned long long r;
    asm("mov.b64 %0, {%1, %2};" : "=l"(r) : "f"(lo), "f"(hi));
    return r;
}
__device__ __forceinline__ void upk2(unsigned long long v, float& lo, float& hi) {
    asm("mov.b64 {%0, %1}, %2;" : "=f"(lo), "=f"(hi) : "l"(v));
}
#define FMA2(d, a, b, c) asm("fma.rn.f32x2 %0, %1, %2, %3;" : "=l"(d) : "l"(a), "l"(b), "l"(c))
#define MUL2(d, a, b)    asm("mul.rn.f32x2 %0, %1, %2;" : "=l"(d) : "l"(a), "l"(b))
#define ADD2(d, a, b)    asm("add.rn.f32x2 %0, %1, %2;" : "=l"(d) : "l"(a), "l"(b))

#define HALF2C 0x3F0000003F000000ULL   // (0.5f, 0.5f)

// ---- pass 1: stats of h = relu(ctx@W1+b1) + store r as fp16 ---------------
// warp-per-edge-stream, lane owns 8 columns, weights in packed smem.
__global__ void __launch_bounds__(128) kStats(
    const float* __restrict__ nf, const int* __restrict__ ei,
    const float* __restrict__ W1, const float* __restrict__ b1, int E) {
    __shared__ ulonglong2 sWa[256];   // col j: pairs (w0,w1),(w2,w3)
    __shared__ ulonglong2 sWb[256];   // col j: pairs (w4,w5),(w6,w7)
    __shared__ float sBb[256];
    __shared__ float psum[4][256];
    __shared__ float psq[4][256];

    int tid = threadIdx.x;
    int lane = tid & 31;
    int w = tid >> 5;

    for (int j = tid; j < 256; j += 128) {
        ulonglong2 va, vb;
        va.x = pk2(W1[0 * 256 + j], W1[1 * 256 + j]);
        va.y = pk2(W1[2 * 256 + j], W1[3 * 256 + j]);
        vb.x = pk2(W1[4 * 256 + j], W1[5 * 256 + j]);
        vb.y = pk2(W1[6 * 256 + j], W1[7 * 256 + j]);
        sWa[j] = va;
        sWb[j] = vb;
        sBb[j] = b1[j];
    }
    __syncthreads();

    float s[8], q[8];
#pragma unroll
    for (int k = 0; k < 8; k++) { s[k] = 0.f; q[k] = 0.f; }

    int gw = blockIdx.x * 4 + w;
    int per = (E + STATS_WARPS - 1) / STATS_WARPS;
    int e0 = gw * per;
    int e1 = min(e0 + per, E);

    const ulonglong4* nfq = (const ulonglong4*)nf;
    const unsigned long long H2 = HALF2C;

    for (int e = e0; e < e1; e += 2) {
        int ia0 = ei[e], ib0 = ei[E + e];
        bool two = (e + 1 < e1);
        int et = two ? (e + 1) : e;
        int ia1 = ei[et], ib1 = ei[E + et];

        ulonglong4 A0 = nfq[ia0], B0 = nfq[ib0];
        ulonglong4 A1 = nfq[ia1], B1 = nfq[ib1];

        unsigned long long c0[4], c1[4];
        ADD2(c0[0], A0.x, B0.x); ADD2(c0[1], A0.y, B0.y);
        ADD2(c0[2], A0.z, B0.z); ADD2(c0[3], A0.w, B0.w);
        ADD2(c1[0], A1.x, B1.x); ADD2(c1[1], A1.y, B1.y);
        ADD2(c1[2], A1.z, B1.z); ADD2(c1[3], A1.w, B1.w);
#pragma unroll
        for (int p = 0; p < 4; p++) { MUL2(c0[p], c0[p], H2); MUL2(c1[p], c1[p], H2); }

#pragma unroll
        for (int p = 0; p < 4; p++) {
            int j0 = p * 64 + lane;      // col k=2p
            int j1 = j0 + 32;            // col k=2p+1
            ulonglong2 wa0 = sWa[j0], wb0 = sWb[j0];
            ulonglong2 wa1 = sWa[j1], wb1 = sWb[j1];
            float bb0 = sBb[j0], bb1 = sBb[j1];
            unsigned long long t0, t1;
            float lo, hi;

            // edge0, col 2p
            MUL2(t0, c0[0], wa0.x); FMA2(t0, c0[1], wa0.y, t0);
            MUL2(t1, c0[2], wb0.x); FMA2(t1, c0[3], wb0.y, t1);
            ADD2(t0, t0, t1); upk2(t0, lo, hi);
            float hA0 = fmaxf(lo + hi + bb0, 0.f);
            // edge0, col 2p+1
            MUL2(t0, c0[0], wa1.x); FMA2(t0, c0[1], wa1.y, t0);
            MUL2(t1, c0[2], wb1.x); FMA2(t1, c0[3], wb1.y, t1);
            ADD2(t0, t0, t1); upk2(t0, lo, hi);
            float hA1 = fmaxf(lo + hi + bb1, 0.f);
            // edge1, col 2p
            MUL2(t0, c1[0], wa0.x); FMA2(t0, c1[1], wa0.y, t0);
            MUL2(t1, c1[2], wb0.x); FMA2(t1, c1[3], wb0.y, t1);
            ADD2(t0, t0, t1); upk2(t0, lo, hi);
            float hB0 = fmaxf(lo + hi + bb0, 0.f);
            // edge1, col 2p+1
            MUL2(t0, c1[0], wa1.x); FMA2(t0, c1[1], wa1.y, t0);
            MUL2(t1, c1[2], wb1.x); FMA2(t1, c1[3], wb1.y, t1);
            ADD2(t0, t0, t1); upk2(t0, lo, hi);
            float hB1 = fmaxf(lo + hi + bb1, 0.f);

            s[2 * p] += hA0;     q[2 * p]     = fmaf(hA0, hA0, q[2 * p]);
            s[2 * p + 1] += hA1; q[2 * p + 1] = fmaf(hA1, hA1, q[2 * p + 1]);

            __half2 hw0 = __floats2half2_rn(hA0, hA1);
            g_h[(size_t)e * 128 + p * 32 + lane] = *reinterpret_cast<unsigned*>(&hw0);

            if (two) {
                s[2 * p] += hB0;     q[2 * p]     = fmaf(hB0, hB0, q[2 * p]);
                s[2 * p + 1] += hB1; q[2 * p + 1] = fmaf(hB1, hB1, q[2 * p + 1]);
                __half2 hw1 = __floats2half2_rn(hB0, hB1);
                g_h[(size_t)(e + 1) * 128 + p * 32 + lane] =
                    *reinterpret_cast<unsigned*>(&hw1);
            }
        }
    }

#pragma unroll
    for (int k = 0; k < 8; k++) {
        psum[w][k * 32 + lane] = s[k];
        psq[w][k * 32 + lane] = q[k];
    }
    __syncthreads();

    for (int c = tid; c < 256; c += 128) {
        float ts = 0.f, tq = 0.f;
#pragma unroll
        for (int ww = 0; ww < 4; ww++) { ts += psum[ww][c]; tq += psq[ww][c]; }
        g_part[blockIdx.x * 512 + c] = ts;
        g_part[blockIdx.x * 512 + 256 + c] = tq;
    }
}

// ---- weight folding + BN finalize, single kernel --------------------------
__global__ void __launch_bounds__(1024) kFoldFin(
    const float* __restrict__ Wo, const float* __restrict__ Wp,
    const float* __restrict__ nb2, const float* __restrict__ Wv,
    const float* __restrict__ bv, const float* __restrict__ bo,
    const float* __restrict__ nW2, const float* __restrict__ bp,
    const float* __restrict__ gamma, const float* __restrict__ beta,
    float invE) {
    int tid = threadIdx.x;

    // stage A: U = Wo@Wp ; c1 = nb2@Wv + bv
    for (int t = tid; t < 2304; t += 1024) {
        if (t < 2048) {
            int i = t >> 3, d = t & 7;
            float a0 = 0.f, a1 = 0.f, a2 = 0.f, a3 = 0.f;
            for (int k = 0; k < 256; k += 4) {
                a0 = fmaf(Wo[i * 256 + k],     Wp[k * 8 + d],       a0);
                a1 = fmaf(Wo[i * 256 + k + 1], Wp[(k + 1) * 8 + d], a1);
                a2 = fmaf(Wo[i * 256 + k + 2], Wp[(k + 2) * 8 + d], a2);
                a3 = fmaf(Wo[i * 256 + k + 3], Wp[(k + 3) * 8 + d], a3);
            }
            g_U[t] = (a0 + a1) + (a2 + a3);
        } else {
            int i = t - 2048;
            float a0 = bv[i], a1 = 0.f, a2 = 0.f, a3 = 0.f;
            for (int k = 0; k < 256; k += 4) {
                a0 = fmaf(nb2[k],     Wv[k * 256 + i],       a0);
                a1 = fmaf(nb2[k + 1], Wv[(k + 1) * 256 + i], a1);
                a2 = fmaf(nb2[k + 2], Wv[(k + 2) * 256 + i], a2);
                a3 = fmaf(nb2[k + 3], Wv[(k + 3) * 256 + i], a3);
            }
            g_c1[i] = (a0 + a1) + (a2 + a3);
        }
    }
    __syncthreads();

    // stage B: V = Wv@U ; c2 = c1@Wo + bo
    for (int t = tid; t < 2304; t += 1024) {
        if (t < 2048) {
            int i = t >> 3, d = t & 7;
            float a0 = 0.f, a1 = 0.f, a2 = 0.f, a3 = 0.f;
            for (int k = 0; k < 256; k += 4) {
                a0 = fmaf(Wv[i * 256 + k],     g_U[k * 8 + d],       a0);
                a1 = fmaf(Wv[i * 256 + k + 1], g_U[(k + 1) * 8 + d], a1);
                a2 = fmaf(Wv[i * 256 + k + 2], g_U[(k + 2) * 8 + d], a2);
                a3 = fmaf(Wv[i * 256 + k + 3], g_U[(k + 3) * 8 + d], a3);
            }
            g_V[t] = (a0 + a1) + (a2 + a3);
        } else {
            int i = t - 2048;
            float a0 = bo[i], a1 = 0.f, a2 = 0.f, a3 = 0.f;
            for (int k = 0; k < 256; k += 4) {
                a0 = fmaf(g_c1[k],     Wo[k * 256 + i],       a0);
                a1 = fmaf(g_c1[k + 1], Wo[(k + 1) * 256 + i], a1);
                a2 = fmaf(g_c1[k + 2], Wo[(k + 2) * 256 + i], a2);
                a3 = fmaf(g_c1[k + 3], Wo[(k + 3) * 256 + i], a3);
            }
            g_c2[i] = (a0 + a1) + (a2 + a3);
        }
    }
    __syncthreads();

    // stage C: M = nW2@V ; c3 = c2@Wp + bp
    for (int t = tid; t < 2056; t += 1024) {
        if (t < 2048) {
            int i = t >> 3, d = t & 7;
            float a0 = 0.f, a1 = 0.f, a2 = 0.f, a3 = 0.f;
            for (int k = 0; k < 256; k += 4) {
                a0 = fmaf(nW2[i * 256 + k],     g_V[k * 8 + d],       a0);
                a1 = fmaf(nW2[i * 256 + k + 1], g_V[(k + 1) * 8 + d], a1);
                a2 = fmaf(nW2[i * 256 + k + 2], g_V[(k + 2) * 8 + d], a2);
                a3 = fmaf(nW2[i * 256 + k + 3], g_V[(k + 3) * 8 + d], a3);
            }
            g_M[t] = (a0 + a1) + (a2 + a3);
        } else {
            int d = t - 2048;
            float acc = bp[d];
            for (int k = 0; k < 256; k++) acc = fmaf(g_c2[k], Wp[k * 8 + d], acc);
            g_c3[d] = acc;
        }
    }
    __syncthreads();

    // finalize BN: fold into permuted Mgp / const8
    __shared__ float sh[256];
    if (tid < 256) {
        int j = tid;
        float s = 0.f, q = 0.f;
        for (int b = 0; b < STATS_BLOCKS; b++) {
            s += g_part[b * 512 + j];
            q += g_part[b * 512 + 256 + j];
        }
        float mu = s * invE;
        float var = q * invE - mu * mu;
        float gg = gamma[j] * rsqrtf(var + 1e-5f);
        sh[j] = beta[j] - mu * gg;
        // permute to word-major: word i = (j>>6)*32 + (j&31), half = (j>>5)&1
        int i = ((j >> 6) << 5) + (j & 31);
        int hf = (j >> 5) & 1;
#pragma unroll
        for (int d = 0; d < 8; d++)
            g_Mgp[i * 16 + hf * 8 + d] = gg * g_M[j * 8 + d];
    }
    __syncthreads();
    if (tid < 256) {
        int w = tid >> 5, lane = tid & 31;   // warp w -> const8[w]
        float acc = 0.f;
        for (int jj = lane; jj < 256; jj += 32) acc += sh[jj] * g_M[jj * 8 + w];
#pragma unroll
        for (int off = 16; off; off >>= 1)
            acc += __shfl_xor_sync(0xffffffffu, acc, off);
        if (lane == 0) g_const8[w] = acc + g_c3[w];
    }
}

// ---- pass 2: stream stored r, y = r @ Mgp ---------------------------------
__global__ void __launch_bounds__(256) kOut(
    const float* __restrict__ ea, float* __restrict__ out, int E) {
    __shared__ ulonglong2 sMg[512];   // word i -> [4i..4i+3] (16 floats)
    __shared__ unsigned long long sC[4];

    int tid = threadIdx.x;
    for (int i = tid; i < 512; i += 256)
        sMg[i] = ((const ulonglong2*)g_Mgp)[i];
    if (tid < 4) sC[tid] = ((const unsigned long long*)g_const8)[tid];
    __syncthreads();

    int e = blockIdx.x * 256 + tid;
    if (e >= E) return;

    const uint4* hq = (const uint4*)(g_h + (size_t)e * 128);
    unsigned long long y[4];
#pragma unroll
    for (int d = 0; d < 4; d++) y[d] = 0ull;

#pragma unroll 4
    for (int i4 = 0; i4 < 32; i4++) {
        uint4 hw = hq[i4];
        unsigned wv[4] = {hw.x, hw.y, hw.z, hw.w};
#pragma unroll
        for (int t = 0; t < 4; t++) {
            int word = i4 * 4 + t;
            __half2 hh = *reinterpret_cast<const __half2*>(&wv[t]);
            float2 f = __half22float2(hh);
            unsigned long long hx = pk2(f.x, f.x);
            unsigned long long hy = pk2(f.y, f.y);
            ulonglong2 m0 = sMg[word * 4 + 0];
            ulonglong2 m1 = sMg[word * 4 + 1];
            ulonglong2 m2 = sMg[word * 4 + 2];
            ulonglong2 m3 = sMg[word * 4 + 3];
            FMA2(y[0], hx, m0.x, y[0]); FMA2(y[1], hx, m0.y, y[1]);
            FMA2(y[2], hx, m1.x, y[2]); FMA2(y[3], hx, m1.y, y[3]);
            FMA2(y[0], hy, m2.x, y[0]); FMA2(y[1], hy, m2.y, y[1]);
            FMA2(y[2], hy, m3.x, y[2]); FMA2(y[3], hy, m3.y, y[3]);
        }
    }

    const unsigned long long H2 = HALF2C;
    const ulonglong4* eaq = (const ulonglong4*)ea;
    ulonglong4* outq = (ulonglong4*)out;
    ulonglong4 ev = eaq[e];
    ulonglong4 ov;
    unsigned long long t;
    ADD2(t, y[0], sC[0]); FMA2(ov.x, t, H2, ev.x);
    ADD2(t, y[1], sC[1]); FMA2(ov.y, t, H2, ev.y);
    ADD2(t, y[2], sC[2]); FMA2(ov.z, t, H2, ev.z);
    ADD2(t, y[3], sC[3]); FMA2(ov.w, t, H2, ev.w);
    outq[e] = ov;
}

// ---------------------------------------------------------------------------
extern "C" void kernel_launch(void* const* d_in, const int* in_sizes, int n_in,
                              void* d_out, int out_size) {
    const float* edge_attr = (const float*)d_in[0];
    const float* nf        = (const float*)d_in[1];
    const int*   ei        = (const int*)d_in[2];
    // d_in[3..8]: edge-encoder params (dead code in reference)
    const float* nW1   = (const float*)d_in[9];
    const float* nb1   = (const float*)d_in[10];
    const float* ngam  = (const float*)d_in[11];
    const float* nbet  = (const float*)d_in[12];
    const float* nW2   = (const float*)d_in[13];
    const float* nb2   = (const float*)d_in[14];
    const float* Wv    = (const float*)d_in[15];
    const float* bv    = (const float*)d_in[16];
    const float* Wo    = (const float*)d_in[17];
    const float* bo    = (const float*)d_in[18];
    const float* Wp    = (const float*)d_in[19];
    const float* bp    = (const float*)d_in[20];
    float* out = (float*)d_out;

    int E = in_sizes[0] / 8;

    kStats<<<STATS_BLOCKS, 128>>>(nf, ei, nW1, nb1, E);
    kFoldFin<<<1, 1024>>>(Wo, Wp, nb2, Wv, bv, bo, nW2, bp, ngam, nbet,
                          1.0f / (float)E);
    kOut<<<(E + 255) / 256, 256>>>(edge_attr, out, E);
}